// round 9
// baseline (speedup 1.0000x reference)
#include <cuda_runtime.h>
#include <math.h>

#define HDIM 1024
#define SDIM 2048
#define VDIM 50257
#define IN0  2048
#define SCH  64              // s-chunks for context partials
#define NBLK_L 6283          // ceil(VDIM/8) logits blocks

// ---- scratch (no allocations allowed) ----
__device__ float g_h0[HDIM];
__device__ float g_cat[2 * HDIM];     // [h1, context]
__device__ float g_energies[SDIM];
__device__ float g_attn[SDIM];
__device__ float g_ctx_part[SCH * HDIM];
__device__ float g_logits[VDIM];
__device__ float g_red_m[NBLK_L];
__device__ float g_red_s[NBLK_L];

__device__ __forceinline__ float warpSum(float v) {
#pragma unroll
    for (int o = 16; o > 0; o >>= 1) v += __shfl_down_sync(0xffffffffu, v, o);
    return v;
}
__device__ __forceinline__ float warpMax(float v) {
#pragma unroll
    for (int o = 16; o > 0; o >>= 1) v = fmaxf(v, __shfl_down_sync(0xffffffffu, v, o));
    return v;
}
__device__ __forceinline__ float dot4(float4 a, float4 b) {
    return a.x * b.x + a.y * b.y + a.z * b.z + a.w * b.w;
}
// associative (max, sumexp) merge
__device__ __forceinline__ void msMerge(float& M, float& S, float m2, float s2) {
    float Mn = fmaxf(M, m2);
    S = S * expf(M - Mn) + s2 * expf(m2 - Mn);
    M = Mn;
}

// ---- 1/2. fused GRU cell: block per hidden unit, fully batched loads ----
template <int IN, int LAYER>
__global__ void __launch_bounds__(256) k_gru(
        const float* __restrict__ Wih, const float* __restrict__ Whh,
        const float* __restrict__ bih, const float* __restrict__ bhh,
        const float* __restrict__ hprev, float* __restrict__ dout_h,
        const int* __restrict__ word, const float* __restrict__ emb,
        const float* __restrict__ last_context) {
    const int j = blockIdx.x;
    const int tid = threadIdx.x;        // 256
    __shared__ float4 xs[IN / 4];       // input vector
    __shared__ float4 hs[HDIM / 4];     // hidden vector

    // stage x and h
    if (LAYER == 0) {
        const float4* ew = (const float4*)(emb + (size_t)word[0] * HDIM);
        xs[tid] = ew[tid];
        xs[tid + 256] = ((const float4*)last_context)[tid];
    } else {
        xs[tid] = ((const float4*)g_h0)[tid];
    }
    hs[tid] = ((const float4*)hprev)[tid];

    // early independent scalar loads (thread 0 only)
    float bi0, bi1, bi2, bh0, bh1, bh2, hj;
    if (tid == 0) {
        bi0 = bih[j]; bi1 = bih[HDIM + j]; bi2 = bih[2 * HDIM + j];
        bh0 = bhh[j]; bh1 = bhh[HDIM + j]; bh2 = bhh[2 * HDIM + j];
        hj  = hprev[j];
    }
    __syncthreads();

    const float4* wr = (const float4*)(Wih + (size_t)j * IN);
    const float4* wz = (const float4*)(Wih + (size_t)(HDIM + j) * IN);
    const float4* wn = (const float4*)(Wih + (size_t)(2 * HDIM + j) * IN);
    const float4* ur = (const float4*)(Whh + (size_t)j * HDIM);
    const float4* uz = (const float4*)(Whh + (size_t)(HDIM + j) * HDIM);
    const float4* un = (const float4*)(Whh + (size_t)(2 * HDIM + j) * HDIM);

    float s0, s1, s2, s3, s4, s5;
    if (LAYER == 0) {
        float4 r0a = __ldcs(wr + tid), r0b = __ldcs(wr + tid + 256);
        float4 r1a = __ldcs(wz + tid), r1b = __ldcs(wz + tid + 256);
        float4 r2a = __ldcs(wn + tid), r2b = __ldcs(wn + tid + 256);
        float4 r3  = __ldcs(ur + tid);
        float4 r4  = __ldcs(uz + tid);
        float4 r5  = __ldcs(un + tid);
        float4 xa = xs[tid], xb = xs[tid + 256], hv = hs[tid];
        s0 = dot4(r0a, xa) + dot4(r0b, xb);
        s1 = dot4(r1a, xa) + dot4(r1b, xb);
        s2 = dot4(r2a, xa) + dot4(r2b, xb);
        s3 = dot4(r3, hv);
        s4 = dot4(r4, hv);
        s5 = dot4(r5, hv);
    } else {
        float4 r0 = __ldcs(wr + tid);
        float4 r1 = __ldcs(wz + tid);
        float4 r2 = __ldcs(wn + tid);
        float4 r3 = __ldcs(ur + tid);
        float4 r4 = __ldcs(uz + tid);
        float4 r5 = __ldcs(un + tid);
        float4 xa = xs[tid], hv = hs[tid];
        s0 = dot4(r0, xa);
        s1 = dot4(r1, xa);
        s2 = dot4(r2, xa);
        s3 = dot4(r3, hv);
        s4 = dot4(r4, hv);
        s5 = dot4(r5, hv);
    }

    __shared__ float sh[6][8];
    int lane = tid & 31, w = tid >> 5;
    float v;
    v = warpSum(s0); if (lane == 0) sh[0][w] = v;
    v = warpSum(s1); if (lane == 0) sh[1][w] = v;
    v = warpSum(s2); if (lane == 0) sh[2][w] = v;
    v = warpSum(s3); if (lane == 0) sh[3][w] = v;
    v = warpSum(s4); if (lane == 0) sh[4][w] = v;
    v = warpSum(s5); if (lane == 0) sh[5][w] = v;
    __syncthreads();
    if (tid == 0) {
        float t[6];
#pragma unroll
        for (int i = 0; i < 6; i++) {
            float a = 0.f;
#pragma unroll
            for (int q = 0; q < 8; q++) a += sh[i][q];
            t[i] = a;
        }
        float r = 1.f / (1.f + expf(-(t[0] + bi0 + t[3] + bh0)));
        float z = 1.f / (1.f + expf(-(t[1] + bi1 + t[4] + bh1)));
        float n = tanhf(t[2] + bi2 + r * (t[5] + bh2));
        float hnew = (1.f - z) * n + z * hj;
        if (LAYER == 0) g_h0[j] = hnew; else g_cat[j] = hnew;
        dout_h[j] = hnew;
    }
}

// ---- 3. energies: 1 row/warp, explicit 8-deep load batch ----
__global__ void k_energy(const float* __restrict__ enc) {
    __shared__ float4 qs[HDIM / 4];
    const int tid = threadIdx.x;              // 256
    qs[tid] = ((const float4*)g_cat)[tid];
    __syncthreads();
    const int warp = tid >> 5, lane = tid & 31;
    const int row = blockIdx.x * 8 + warp;
    const float4* e = (const float4*)(enc + (size_t)row * HDIM);
    float4 r[8];
#pragma unroll
    for (int i = 0; i < 8; i++) r[i] = __ldcs(e + lane + 32 * i);
    float acc = 0.f;
#pragma unroll
    for (int i = 0; i < 8; i++) acc += dot4(r[i], qs[lane + 32 * i]);
    acc = warpSum(acc);
    if (lane == 0) g_energies[row] = acc;
}

// ---- 4. softmax over 2048 energies: 256 threads x 8 (float4 in, scalar out) ----
__global__ void k_softmax(float* __restrict__ dout_attn) {
    const int tid = threadIdx.x;              // 256
    const int lane = tid & 31, w = tid >> 5;
    float4 a = ((const float4*)g_energies)[tid];
    float4 b = ((const float4*)g_energies)[tid + 256];
    __shared__ float sh[8];

    float m = fmaxf(fmaxf(fmaxf(a.x, a.y), fmaxf(a.z, a.w)),
                    fmaxf(fmaxf(b.x, b.y), fmaxf(b.z, b.w)));
    m = warpMax(m);
    if (lane == 0) sh[w] = m;
    __syncthreads();
    float M = fmaxf(fmaxf(fmaxf(sh[0], sh[1]), fmaxf(sh[2], sh[3])),
                    fmaxf(fmaxf(sh[4], sh[5]), fmaxf(sh[6], sh[7])));
    __syncthreads();

    float4 ea, eb;
    ea.x = expf(a.x - M); ea.y = expf(a.y - M); ea.z = expf(a.z - M); ea.w = expf(a.w - M);
    eb.x = expf(b.x - M); eb.y = expf(b.y - M); eb.z = expf(b.z - M); eb.w = expf(b.w - M);
    float s = (ea.x + ea.y + ea.z + ea.w) + (eb.x + eb.y + eb.z + eb.w);
    s = warpSum(s);
    if (lane == 0) sh[w] = s;
    __syncthreads();
    float inv = 1.f / ((sh[0] + sh[1] + sh[2] + sh[3]) +
                       (sh[4] + sh[5] + sh[6] + sh[7]));
    ea.x *= inv; ea.y *= inv; ea.z *= inv; ea.w *= inv;
    eb.x *= inv; eb.y *= inv; eb.z *= inv; eb.w *= inv;
    ((float4*)g_attn)[tid] = ea;       ((float4*)g_attn)[tid + 256] = eb;
    // dout_attn is out+53329 floats: NOT 16B-aligned -> scalar stores only
    int i0 = tid * 4, i1 = 1024 + tid * 4;
    dout_attn[i0 + 0] = ea.x; dout_attn[i0 + 1] = ea.y;
    dout_attn[i0 + 2] = ea.z; dout_attn[i0 + 3] = ea.w;
    dout_attn[i1 + 0] = eb.x; dout_attn[i1 + 1] = eb.y;
    dout_attn[i1 + 2] = eb.z; dout_attn[i1 + 3] = eb.w;
}

// ---- 5a. context partials: grid (4 h-chunks, SCH s-chunks), batched ----
__global__ void k_context_part(const float* __restrict__ enc) {
    __shared__ float sa[SDIM / SCH];          // 32 attn weights
    const int tid = threadIdx.x;              // 256
    const int s0 = blockIdx.y * (SDIM / SCH);
    if (tid < SDIM / SCH) sa[tid] = g_attn[s0 + tid];
    __syncthreads();
    const int h = blockIdx.x * 256 + tid;
    const float* e = enc + (size_t)s0 * HDIM + h;
    float acc = 0.f;
#pragma unroll
    for (int bq = 0; bq < 4; bq++) {
        float r[8];
#pragma unroll
        for (int i = 0; i < 8; i++) r[i] = __ldcs(e + (size_t)(bq * 8 + i) * HDIM);
#pragma unroll
        for (int i = 0; i < 8; i++) acc += sa[bq * 8 + i] * r[i];
    }
    g_ctx_part[blockIdx.y * HDIM + h] = acc;
}

// ---- 5b. context reduce over SCH partials (batched) ----
__global__ void k_context_red(float* __restrict__ dout_ctx) {
    int h = blockIdx.x * 256 + threadIdx.x;
    float acc = 0.f;
#pragma unroll
    for (int bq = 0; bq < SCH / 8; bq++) {
        float r[8];
#pragma unroll
        for (int i = 0; i < 8; i++) r[i] = g_ctx_part[(bq * 8 + i) * HDIM + h];
#pragma unroll
        for (int i = 0; i < 8; i++) acc += r[i];
    }
    g_cat[HDIM + h] = acc;
    dout_ctx[h] = acc;
}

// ---- 6. logits GEMV + per-block (max,sumexp) partial ----
__global__ void __launch_bounds__(256) k_logits(const float* __restrict__ Wout,
                                                const float* __restrict__ bout) {
    __shared__ float4 cs[512];                // [h1, context]
    __shared__ float sl[8];                   // per-warp logits
    const int tid = threadIdx.x;              // 256
    cs[tid] = ((const float4*)g_cat)[tid];
    cs[tid + 256] = ((const float4*)g_cat)[tid + 256];
    __syncthreads();
    const int warp = tid >> 5, lane = tid & 31;
    const int row = blockIdx.x * 8 + warp;
    const bool valid = row < VDIM;
    const int rowc = valid ? row : (VDIM - 1);
    const float4* w4 = (const float4*)(Wout + (size_t)rowc * (2 * HDIM));
    float acc = 0.f;
#pragma unroll
    for (int bq = 0; bq < 2; bq++) {
        float4 r[8];
#pragma unroll
        for (int i = 0; i < 8; i++) r[i] = __ldcs(w4 + bq * 256 + lane + 32 * i);
#pragma unroll
        for (int i = 0; i < 8; i++) acc += dot4(r[i], cs[bq * 256 + lane + 32 * i]);
    }
    acc = warpSum(acc);
    if (lane == 0) {
        float lg = valid ? (acc + bout[row]) : -INFINITY;
        if (valid) g_logits[row] = lg;
        sl[warp] = lg;
    }
    __syncthreads();
    if (tid == 0) {
        float M = sl[0], S = (sl[0] == -INFINITY) ? 0.f : 1.f;
#pragma unroll
        for (int q = 1; q < 8; q++) {
            float lq = sl[q];
            if (lq != -INFINITY) msMerge(M, S, lq, 1.f);
        }
        g_red_m[blockIdx.x] = M;
        g_red_s[blockIdx.x] = S;
    }
}

// ---- 7. k_out: self-reducing lse (batched associative merge) + write ----
__global__ void __launch_bounds__(256) k_out(float* __restrict__ dout) {
    __shared__ float shm[8], shs[8], sh_lse;
    const int tid = threadIdx.x;
    const int lane = tid & 31, w = tid >> 5;
    const int NPT = (NBLK_L + 255) / 256;     // 25 partials per thread
    float rm[NPT], rs[NPT];
#pragma unroll
    for (int k = 0; k < NPT; k++) {
        int i = tid + k * 256;
        bool v = i < NBLK_L;
        rm[k] = v ? g_red_m[i] : -INFINITY;
        rs[k] = v ? g_red_s[i] : 0.f;
    }
    float M = rm[0], S = rs[0];
#pragma unroll
    for (int k = 1; k < NPT; k++) msMerge(M, S, rm[k], rs[k]);
#pragma unroll
    for (int o = 16; o > 0; o >>= 1) {
        float M2 = __shfl_down_sync(0xffffffffu, M, o);
        float S2 = __shfl_down_sync(0xffffffffu, S, o);
        msMerge(M, S, M2, S2);
    }
    if (lane == 0) { shm[w] = M; shs[w] = S; }
    __syncthreads();
    if (tid == 0) {
        float Mf = shm[0], Sf = shs[0];
#pragma unroll
        for (int q = 1; q < 8; q++) msMerge(Mf, Sf, shm[q], shs[q]);
        sh_lse = Mf + logf(Sf);
    }
    __syncthreads();
    float lse = sh_lse;
    int v = blockIdx.x * 256 + tid;
    if (v < VDIM) dout[v] = g_logits[v] - lse;
}

extern "C" void kernel_launch(void* const* d_in, const int* in_sizes, int n_in,
                              void* d_out, int out_size) {
    const int*   word         = (const int*)d_in[0];
    const float* last_context = (const float*)d_in[1];
    const float* last_hidden  = (const float*)d_in[2];   // (2,1,H)
    const float* enc          = (const float*)d_in[3];   // (S,1,H)
    const float* emb  = (const float*)d_in[4];
    const float* Wih0 = (const float*)d_in[5];
    const float* Whh0 = (const float*)d_in[6];
    const float* bih0 = (const float*)d_in[7];
    const float* bhh0 = (const float*)d_in[8];
    const float* Wih1 = (const float*)d_in[9];
    const float* Whh1 = (const float*)d_in[10];
    const float* bih1 = (const float*)d_in[11];
    const float* bhh1 = (const float*)d_in[12];
    const float* Wout = (const float*)d_in[13];
    const float* bout = (const float*)d_in[14];

    float* out       = (float*)d_out;
    float* out_ctx   = out + VDIM;
    float* out_h0    = out + VDIM + HDIM;
    float* out_h1    = out + VDIM + 2 * HDIM;
    float* out_attn  = out + VDIM + 3 * HDIM;

    k_gru<IN0, 0><<<HDIM, 256>>>(Wih0, Whh0, bih0, bhh0, last_hidden,         out_h0,
                                 word, emb, last_context);
    k_gru<HDIM, 1><<<HDIM, 256>>>(Wih1, Whh1, bih1, bhh1, last_hidden + HDIM, out_h1,
                                 word, emb, last_context);
    k_energy<<<SDIM / 8, 256>>>(enc);
    k_softmax<<<1, 256>>>(out_attn);
    k_context_part<<<dim3(HDIM / 256, SCH), 256>>>(enc);
    k_context_red<<<HDIM / 256, 256>>>(out_ctx);
    k_logits<<<NBLK_L, 256>>>(Wout, bout);
    k_out<<<(VDIM + 255) / 256, 256>>>(out);
}

// round 12
// speedup vs baseline: 1.0169x; 1.0169x over previous
#include <cuda_runtime.h>
#include <math.h>

#define HDIM 1024
#define SDIM 2048
#define VDIM 50257
#define IN0  2048
#define SCH  64              // s-chunks for context partials
#define NEB  256             // energy blocks (8 rows each)
#define NBLK_L 6283          // ceil(VDIM/8) logits blocks

// ---- scratch (no allocations allowed) ----
__device__ float g_h0[HDIM];
__device__ float g_cat[2 * HDIM];     // [h1, context]
__device__ float g_energies[SDIM];
__device__ float g_em[NEB];           // per-energy-block max
__device__ float g_es[NEB];           // per-energy-block sumexp
__device__ float g_ctx_part[SCH * HDIM];
__device__ float g_logits[VDIM];
__device__ float g_red_m[NBLK_L];
__device__ float g_red_s[NBLK_L];

__device__ __forceinline__ float warpSum(float v) {
#pragma unroll
    for (int o = 16; o > 0; o >>= 1) v += __shfl_down_sync(0xffffffffu, v, o);
    return v;
}
__device__ __forceinline__ float dot4(float4 a, float4 b) {
    return a.x * b.x + a.y * b.y + a.z * b.z + a.w * b.w;
}
// associative (max, sumexp) merge
__device__ __forceinline__ void msMerge(float& M, float& S, float m2, float s2) {
    float Mn = fmaxf(M, m2);
    S = S * expf(M - Mn) + s2 * expf(m2 - Mn);
    M = Mn;
}

// ---- 1/2. fused GRU cell: block per hidden unit, fully batched loads ----
template <int IN, int LAYER>
__global__ void __launch_bounds__(256) k_gru(
        const float* __restrict__ Wih, const float* __restrict__ Whh,
        const float* __restrict__ bih, const float* __restrict__ bhh,
        const float* __restrict__ hprev, float* __restrict__ dout_h,
        const int* __restrict__ word, const float* __restrict__ emb,
        const float* __restrict__ last_context) {
    const int j = blockIdx.x;
    const int tid = threadIdx.x;        // 256
    __shared__ float4 xs[IN / 4];
    __shared__ float4 hs[HDIM / 4];

    if (LAYER == 0) {
        const float4* ew = (const float4*)(emb + (size_t)word[0] * HDIM);
        xs[tid] = ew[tid];
        xs[tid + 256] = ((const float4*)last_context)[tid];
    } else {
        xs[tid] = ((const float4*)g_h0)[tid];
    }
    hs[tid] = ((const float4*)hprev)[tid];

    float bi0, bi1, bi2, bh0, bh1, bh2, hj;
    if (tid == 0) {
        bi0 = bih[j]; bi1 = bih[HDIM + j]; bi2 = bih[2 * HDIM + j];
        bh0 = bhh[j]; bh1 = bhh[HDIM + j]; bh2 = bhh[2 * HDIM + j];
        hj  = hprev[j];
    }
    __syncthreads();

    const float4* wr = (const float4*)(Wih + (size_t)j * IN);
    const float4* wz = (const float4*)(Wih + (size_t)(HDIM + j) * IN);
    const float4* wn = (const float4*)(Wih + (size_t)(2 * HDIM + j) * IN);
    const float4* ur = (const float4*)(Whh + (size_t)j * HDIM);
    const float4* uz = (const float4*)(Whh + (size_t)(HDIM + j) * HDIM);
    const float4* un = (const float4*)(Whh + (size_t)(2 * HDIM + j) * HDIM);

    float s0, s1, s2, s3, s4, s5;
    if (LAYER == 0) {
        float4 r0a = __ldcs(wr + tid), r0b = __ldcs(wr + tid + 256);
        float4 r1a = __ldcs(wz + tid), r1b = __ldcs(wz + tid + 256);
        float4 r2a = __ldcs(wn + tid), r2b = __ldcs(wn + tid + 256);
        float4 r3  = __ldcs(ur + tid);
        float4 r4  = __ldcs(uz + tid);
        float4 r5  = __ldcs(un + tid);
        float4 xa = xs[tid], xb = xs[tid + 256], hv = hs[tid];
        s0 = dot4(r0a, xa) + dot4(r0b, xb);
        s1 = dot4(r1a, xa) + dot4(r1b, xb);
        s2 = dot4(r2a, xa) + dot4(r2b, xb);
        s3 = dot4(r3, hv);
        s4 = dot4(r4, hv);
        s5 = dot4(r5, hv);
    } else {
        float4 r0 = __ldcs(wr + tid);
        float4 r1 = __ldcs(wz + tid);
        float4 r2 = __ldcs(wn + tid);
        float4 r3 = __ldcs(ur + tid);
        float4 r4 = __ldcs(uz + tid);
        float4 r5 = __ldcs(un + tid);
        float4 xa = xs[tid], hv = hs[tid];
        s0 = dot4(r0, xa);
        s1 = dot4(r1, xa);
        s2 = dot4(r2, xa);
        s3 = dot4(r3, hv);
        s4 = dot4(r4, hv);
        s5 = dot4(r5, hv);
    }

    __shared__ float sh[6][8];
    int lane = tid & 31, w = tid >> 5;
    float v;
    v = warpSum(s0); if (lane == 0) sh[0][w] = v;
    v = warpSum(s1); if (lane == 0) sh[1][w] = v;
    v = warpSum(s2); if (lane == 0) sh[2][w] = v;
    v = warpSum(s3); if (lane == 0) sh[3][w] = v;
    v = warpSum(s4); if (lane == 0) sh[4][w] = v;
    v = warpSum(s5); if (lane == 0) sh[5][w] = v;
    __syncthreads();
    if (tid == 0) {
        float t[6];
#pragma unroll
        for (int i = 0; i < 6; i++) {
            float a = 0.f;
#pragma unroll
            for (int q = 0; q < 8; q++) a += sh[i][q];
            t[i] = a;
        }
        float r = 1.f / (1.f + expf(-(t[0] + bi0 + t[3] + bh0)));
        float z = 1.f / (1.f + expf(-(t[1] + bi1 + t[4] + bh1)));
        float n = tanhf(t[2] + bi2 + r * (t[5] + bh2));
        float hnew = (1.f - z) * n + z * hj;
        if (LAYER == 0) g_h0[j] = hnew; else g_cat[j] = hnew;
        dout_h[j] = hnew;
    }
}

// ---- 3. energies + per-block (max,sumexp) partial ----
__global__ void k_energy(const float* __restrict__ enc) {
    __shared__ float4 qs[HDIM / 4];
    __shared__ float sl[8];
    const int tid = threadIdx.x;              // 256
    qs[tid] = ((const float4*)g_cat)[tid];
    __syncthreads();
    const int warp = tid >> 5, lane = tid & 31;
    const int row = blockIdx.x * 8 + warp;
    const float4* e = (const float4*)(enc + (size_t)row * HDIM);
    float4 r[8];
#pragma unroll
    for (int i = 0; i < 8; i++) r[i] = __ldcs(e + lane + 32 * i);
    float acc = 0.f;
#pragma unroll
    for (int i = 0; i < 8; i++) acc += dot4(r[i], qs[lane + 32 * i]);
    acc = warpSum(acc);
    if (lane == 0) { g_energies[row] = acc; sl[warp] = acc; }
    __syncthreads();
    if (tid == 0) {
        float M = sl[0];
#pragma unroll
        for (int q = 1; q < 8; q++) M = fmaxf(M, sl[q]);
        float S = 0.f;
#pragma unroll
        for (int q = 0; q < 8; q++) S += expf(sl[q] - M);
        g_em[blockIdx.x] = M;
        g_es[blockIdx.x] = S;
    }
}

// ---- 4a. context partials (merges softmax stats in-block; no softmax kernel) ----
__global__ void __launch_bounds__(256) k_context_part(const float* __restrict__ enc,
                                                      float* __restrict__ dout_attn) {
    __shared__ float sa[SDIM / SCH];          // 32 attn weights
    __shared__ float shm[8], shs[8], shM, shS;
    const int tid = threadIdx.x;              // 256
    const int lane = tid & 31, w = tid >> 5;

    // merge the 256 (m,s) energy partials -> global (M,S)
    float M = g_em[tid], S = g_es[tid];
#pragma unroll
    for (int o = 16; o > 0; o >>= 1) {
        float M2 = __shfl_down_sync(0xffffffffu, M, o);
        float S2 = __shfl_down_sync(0xffffffffu, S, o);
        msMerge(M, S, M2, S2);
    }
    if (lane == 0) { shm[w] = M; shs[w] = S; }
    __syncthreads();
    if (tid == 0) {
        float Mf = shm[0], Sf = shs[0];
#pragma unroll
        for (int q = 1; q < 8; q++) msMerge(Mf, Sf, shm[q], shs[q]);
        shM = Mf; shS = Sf;
    }
    __syncthreads();
    const float Mg = shM, invS = 1.f / shS;

    const int s0 = blockIdx.y * (SDIM / SCH);
    if (tid < SDIM / SCH) {
        float wgt = expf(g_energies[s0 + tid] - Mg) * invS;
        sa[tid] = wgt;
        if (blockIdx.x == 0) dout_attn[s0 + tid] = wgt;   // scalar store (unaligned dst)
    }
    __syncthreads();

    const int h = blockIdx.x * 256 + tid;
    const float* e = enc + (size_t)s0 * HDIM + h;
    float acc = 0.f;
#pragma unroll
    for (int bq = 0; bq < 4; bq++) {
        float r[8];
#pragma unroll
        for (int i = 0; i < 8; i++) r[i] = __ldcs(e + (size_t)(bq * 8 + i) * HDIM);
#pragma unroll
        for (int i = 0; i < 8; i++) acc += sa[bq * 8 + i] * r[i];
    }
    g_ctx_part[blockIdx.y * HDIM + h] = acc;
}

// ---- 4b. context reduce over SCH partials ----
__global__ void k_context_red(float* __restrict__ dout_ctx) {
    int h = blockIdx.x * 256 + threadIdx.x;
    float acc = 0.f;
#pragma unroll
    for (int bq = 0; bq < SCH / 8; bq++) {
        float r[8];
#pragma unroll
        for (int i = 0; i < 8; i++) r[i] = g_ctx_part[(bq * 8 + i) * HDIM + h];
#pragma unroll
        for (int i = 0; i < 8; i++) acc += r[i];
    }
    g_cat[HDIM + h] = acc;
    dout_ctx[h] = acc;
}

// ---- 5. logits GEMV + per-block (max,sumexp) partial ----
__global__ void __launch_bounds__(256) k_logits(const float* __restrict__ Wout,
                                                const float* __restrict__ bout) {
    __shared__ float4 cs[512];
    __shared__ float sl[8];
    const int tid = threadIdx.x;              // 256
    cs[tid] = ((const float4*)g_cat)[tid];
    cs[tid + 256] = ((const float4*)g_cat)[tid + 256];
    __syncthreads();
    const int warp = tid >> 5, lane = tid & 31;
    const int row = blockIdx.x * 8 + warp;
    const bool valid = row < VDIM;
    const int rowc = valid ? row : (VDIM - 1);
    const float4* w4 = (const float4*)(Wout + (size_t)rowc * (2 * HDIM));
    float acc = 0.f;
#pragma unroll
    for (int bq = 0; bq < 2; bq++) {
        float4 r[8];
#pragma unroll
        for (int i = 0; i < 8; i++) r[i] = __ldcs(w4 + bq * 256 + lane + 32 * i);
#pragma unroll
        for (int i = 0; i < 8; i++) acc += dot4(r[i], cs[bq * 256 + lane + 32 * i]);
    }
    acc = warpSum(acc);
    if (lane == 0) {
        float lg = valid ? (acc + bout[row]) : -INFINITY;
        if (valid) g_logits[row] = lg;
        sl[warp] = lg;
    }
    __syncthreads();
    if (tid == 0) {
        float M = sl[0], S = (sl[0] == -INFINITY) ? 0.f : 1.f;
#pragma unroll
        for (int q = 1; q < 8; q++) {
            float lq = sl[q];
            if (lq != -INFINITY) msMerge(M, S, lq, 1.f);
        }
        g_red_m[blockIdx.x] = M;
        g_red_s[blockIdx.x] = S;
    }
}

// ---- 6. k_out: self-reducing lse + write log-softmax ----
__global__ void __launch_bounds__(256) k_out(float* __restrict__ dout) {
    __shared__ float shm[8], shs[8], sh_lse;
    const int tid = threadIdx.x;
    const int lane = tid & 31, w = tid >> 5;
    const int NPT = (NBLK_L + 255) / 256;     // 25 partials per thread
    float rm[NPT], rs[NPT];
#pragma unroll
    for (int k = 0; k < NPT; k++) {
        int i = tid + k * 256;
        bool v = i < NBLK_L;
        rm[k] = v ? g_red_m[i] : -INFINITY;
        rs[k] = v ? g_red_s[i] : 0.f;
    }
    float M = rm[0], S = rs[0];
#pragma unroll
    for (int k = 1; k < NPT; k++) msMerge(M, S, rm[k], rs[k]);
#pragma unroll
    for (int o = 16; o > 0; o >>= 1) {
        float M2 = __shfl_down_sync(0xffffffffu, M, o);
        float S2 = __shfl_down_sync(0xffffffffu, S, o);
        msMerge(M, S, M2, S2);
    }
    if (lane == 0) { shm[w] = M; shs[w] = S; }
    __syncthreads();
    if (tid == 0) {
        float Mf = shm[0], Sf = shs[0];
#pragma unroll
        for (int q = 1; q < 8; q++) msMerge(Mf, Sf, shm[q], shs[q]);
        sh_lse = Mf + logf(Sf);
    }
    __syncthreads();
    float lse = sh_lse;
    int v = blockIdx.x * 256 + tid;
    if (v < VDIM) dout[v] = g_logits[v] - lse;
}

extern "C" void kernel_launch(void* const* d_in, const int* in_sizes, int n_in,
                              void* d_out, int out_size) {
    const int*   word         = (const int*)d_in[0];
    const float* last_context = (const float*)d_in[1];
    const float* last_hidden  = (const float*)d_in[2];   // (2,1,H)
    const float* enc          = (const float*)d_in[3];   // (S,1,H)
    const float* emb  = (const float*)d_in[4];
    const float* Wih0 = (const float*)d_in[5];
    const float* Whh0 = (const float*)d_in[6];
    const float* bih0 = (const float*)d_in[7];
    const float* bhh0 = (const float*)d_in[8];
    const float* Wih1 = (const float*)d_in[9];
    const float* Whh1 = (const float*)d_in[10];
    const float* bih1 = (const float*)d_in[11];
    const float* bhh1 = (const float*)d_in[12];
    const float* Wout = (const float*)d_in[13];
    const float* bout = (const float*)d_in[14];

    float* out       = (float*)d_out;
    float* out_ctx   = out + VDIM;
    float* out_h0    = out + VDIM + HDIM;
    float* out_h1    = out + VDIM + 2 * HDIM;
    float* out_attn  = out + VDIM + 3 * HDIM;

    k_gru<IN0, 0><<<HDIM, 256>>>(Wih0, Whh0, bih0, bhh0, last_hidden,         out_h0,
                                 word, emb, last_context);
    k_gru<HDIM, 1><<<HDIM, 256>>>(Wih1, Whh1, bih1, bhh1, last_hidden + HDIM, out_h1,
                                 word, emb, last_context);
    k_energy<<<NEB, 256>>>(enc);
    k_context_part<<<dim3(HDIM / 256, SCH), 256>>>(enc, out_attn);
    k_context_red<<<HDIM / 256, 256>>>(out_ctx);
    k_logits<<<NBLK_L, 256>>>(Wout, bout);
    k_out<<<(VDIM + 255) / 256, 256>>>(out);
}